// round 10
// baseline (speedup 1.0000x reference)
#include <cuda_runtime.h>

// Shapes fixed by the problem: x,f = (B=2, 3, T=5, H=720, W=1280) fp32.
// Output = concat(ow, xw), each (B,3,T,H,W) fp32.
constexpr unsigned B  = 2;
constexpr unsigned C  = 3;
constexpr unsigned T  = 5;
constexpr unsigned H  = 720;
constexpr unsigned W  = 1280;
constexpr unsigned PLANE = H * W;            // 921,600
constexpr unsigned CH    = T * PLANE;        // 4,608,000
constexpr unsigned HALF  = B * C * CH;       // 27,648,000

// grid: x -> 10 segments of 128 px, y -> 180 groups of 4 rows, z -> (b,t)
// block: (64, 4) = 256 threads, each thread 2 horizontally adjacent px.

__global__ __launch_bounds__(256)
void ImageBWarp_65343632441725_kernel(const float* __restrict__ x,
                                      const float* __restrict__ f,
                                      float* __restrict__ out)
{
    // zero-division index decode
    unsigned w0 = (blockIdx.x * 64u + threadIdx.x) * 2u;
    unsigned h  = blockIdx.y * 4u + threadIdx.y;
    unsigned bt = blockIdx.z;                 // b*T + t
    unsigned b  = bt / T;
    unsigned base = (bt + b * ((C - 1) * T)) * PLANE;   // (b*C*T + t)*PLANE
    unsigned hw   = h * W + w0;               // 8B-aligned

    const float2 fx2 = *(const float2*)(f + base + hw);
    const float2 fy2 = *(const float2*)(f + base + CH + hw);
    const float2 wl2 = *(const float2*)(f + base + 2u * CH + hw);

    float fx[2] = {fx2.x, fx2.y};
    float fy[2] = {fy2.x, fy2.y};
    float wl[2] = {wl2.x, wl2.y};

    float m00[2], m10[2], m01[2], m11[2];
    // pair-window bases (even -> 8B aligned) for rows y0/y1, fix-up indices
    unsigned e0[2], e1[2], f0[2], f1[2];
    bool sel0[2], eq[2], fixp[2];
    float wgt[2], owv[2];

#pragma unroll
    for (int j = 0; j < 2; j++) {
        float gx = (float)(w0 + (unsigned)j) + fx[j];
        float gy = (float)h + fy[j];

        float x0f = floorf(gx);
        float y0f = floorf(gy);
        float wx1 = gx - x0f;
        float wy1 = gy - y0f;
        float wx0 = 1.0f - wx1;
        float wy0 = 1.0f - wy1;

        int ix0 = (int)x0f;
        int iy0 = (int)y0f;
        int ix1 = ix0 + 1;
        int iy1 = iy0 + 1;

        bool vx0 = (unsigned)ix0 < W;
        bool vx1 = (unsigned)ix1 < W;
        bool vy0 = (unsigned)iy0 < H;
        bool vy1 = (unsigned)iy1 < H;

        m00[j] = (vx0 && vy0) ? wx0 * wy0 : 0.0f;
        m10[j] = (vx1 && vy0) ? wx1 * wy0 : 0.0f;
        m01[j] = (vx0 && vy1) ? wx0 * wy1 : 0.0f;
        m11[j] = (vx1 && vy1) ? wx1 * wy1 : 0.0f;

        unsigned cx0 = (unsigned)min(max(ix0, 0), (int)W - 1);
        unsigned cx1 = (unsigned)min(max(ix1, 0), (int)W - 1);
        unsigned cy0 = (unsigned)min(max(iy0, 0), (int)H - 1);
        unsigned cy1 = (unsigned)min(max(iy1, 0), (int)H - 1);

        sel0[j] = (cx0 & 1u) != 0u;          // window position of x0
        eq[j]   = (cx1 == cx0);              // border collapse
        fixp[j] = sel0[j] && !eq[j];         // odd lanes need a fix-up load

        unsigned exb = cx0 & ~1u;            // even -> float2 aligned, <= W-2
        unsigned r0  = cy0 * W;
        unsigned r1  = cy1 * W;
        e0[j] = r0 + exb;                    // pair window row y0
        e1[j] = r1 + exb;                    // pair window row y1
        f0[j] = r0 + cx1;                    // fix-up (x1) row y0
        f1[j] = r1 + cx1;                    // fix-up (x1) row y1

        // sigmoid via HW tanh
        wgt[j] = 0.5f * __tanhf(0.5f * wl[j]) + 0.5f;
        owv[j] = wgt[j] * (m00[j] + m10[j] + m01[j] + m11[j]);
    }

    // store the 3 identical ow planes first (overlaps gather latency)
    float* out_ow = out + base + hw;
    {
        float2 ow2 = make_float2(owv[0], owv[1]);
        *(float2*)(out_ow)           = ow2;
        *(float2*)(out_ow + CH)      = ow2;
        *(float2*)(out_ow + 2u * CH) = ow2;
    }

    float*       out_xw = out_ow + HALF;
    const float* xb     = x + base;

#pragma unroll
    for (unsigned c = 0; c < C; c++) {
        const float* xc = xb + c * CH;

        // 4 aligned pair loads (each covers both x-taps of one row)
        float2 pa0 = __ldg((const float2*)(xc + e0[0]));
        float2 pa1 = __ldg((const float2*)(xc + e1[0]));
        float2 pb0 = __ldg((const float2*)(xc + e0[1]));
        float2 pb1 = __ldg((const float2*)(xc + e1[1]));
        // predicated fix-up loads: only ~half the lanes active
        float qa0 = fixp[0] ? __ldg(xc + f0[0]) : 0.0f;
        float qa1 = fixp[0] ? __ldg(xc + f1[0]) : 0.0f;
        float qb0 = fixp[1] ? __ldg(xc + f0[1]) : 0.0f;
        float qb1 = fixp[1] ? __ldg(xc + f1[1]) : 0.0f;

        // px j=0
        float v00a = sel0[0] ? pa0.y : pa0.x;
        float v10a = sel0[0] ? qa0   : (eq[0] ? pa0.x : pa0.y);
        float v01a = sel0[0] ? pa1.y : pa1.x;
        float v11a = sel0[0] ? qa1   : (eq[0] ? pa1.x : pa1.y);
        // px j=1
        float v00b = sel0[1] ? pb0.y : pb0.x;
        float v10b = sel0[1] ? qb0   : (eq[1] ? pb0.x : pb0.y);
        float v01b = sel0[1] ? pb1.y : pb1.x;
        float v11b = sel0[1] ? qb1   : (eq[1] ? pb1.x : pb1.y);

        float sa = m00[0] * v00a + m10[0] * v10a + m01[0] * v01a + m11[0] * v11a;
        float sb = m00[1] * v00b + m10[1] * v10b + m01[1] * v01b + m11[1] * v11b;

        *(float2*)(out_xw + c * CH) = make_float2(sa * wgt[0], sb * wgt[1]);
    }
}

extern "C" void kernel_launch(void* const* d_in, const int* in_sizes, int n_in,
                              void* d_out, int out_size)
{
    const float* x = (const float*)d_in[0];
    const float* f = (const float*)d_in[1];
    float* out = (float*)d_out;

    dim3 block(64, 4, 1);
    dim3 grid(W / 128, H / 4, B * T);   // (10, 180, 10)
    ImageBWarp_65343632441725_kernel<<<grid, block>>>(x, f, out);
}

// round 11
// speedup vs baseline: 1.1136x; 1.1136x over previous
#include <cuda_runtime.h>

// Shapes fixed by the problem: x,f = (B=2, 3, T=5, H=720, W=1280) fp32.
// Output = concat(ow, xw), each (B,3,T,H,W) fp32.
constexpr unsigned B  = 2;
constexpr unsigned C  = 3;
constexpr unsigned T  = 5;
constexpr unsigned H  = 720;
constexpr unsigned W  = 1280;
constexpr unsigned PLANE = H * W;            // 921,600
constexpr unsigned CH    = T * PLANE;        // 4,608,000
constexpr unsigned HALF  = B * C * CH;       // 27,648,000

// f: read exactly once -> evict-first, keep L2 for x
__device__ __forceinline__ float2 ldg_cs2(const float* p) {
    float2 v;
    asm("ld.global.cs.v2.f32 {%0,%1}, [%2];" : "=f"(v.x), "=f"(v.y) : "l"(p));
    return v;
}
// outputs: write-once -> evict-first, keep L2 for x
__device__ __forceinline__ void stg_cs2(float* p, float a, float b) {
    asm volatile("st.global.cs.v2.f32 [%0], {%1,%2};" :: "l"(p), "f"(a), "f"(b) : "memory");
}

// grid: x -> 10 segments of 128 px, y -> 180 groups of 4 rows, z -> (b,t)
// block: (64, 4) = 256 threads, each thread 2 horizontally adjacent px.

__global__ __launch_bounds__(256)
void ImageBWarp_65343632441725_kernel(const float* __restrict__ x,
                                      const float* __restrict__ f,
                                      float* __restrict__ out)
{
    // zero-division index decode
    unsigned w0 = (blockIdx.x * 64u + threadIdx.x) * 2u;
    unsigned h  = blockIdx.y * 4u + threadIdx.y;
    unsigned bt = blockIdx.z;                 // b*T + t
    unsigned b  = bt / T;
    unsigned base = (bt + b * ((C - 1) * T)) * PLANE;   // (b*C*T + t)*PLANE
    unsigned hw   = h * W + w0;               // 8B-aligned

    const float2 fx2 = ldg_cs2(f + base + hw);
    const float2 fy2 = ldg_cs2(f + base + CH + hw);
    const float2 wl2 = ldg_cs2(f + base + 2u * CH + hw);

    float fx[2] = {fx2.x, fx2.y};
    float fy[2] = {fy2.x, fy2.y};
    float wl[2] = {wl2.x, wl2.y};

    float m00[2], m10[2], m01[2], m11[2];
    unsigned o00[2], o10[2], o01[2], o11[2];
    float wgt[2], owv[2];

#pragma unroll
    for (int j = 0; j < 2; j++) {
        float gx = (float)(w0 + (unsigned)j) + fx[j];
        float gy = (float)h + fy[j];

        float x0f = floorf(gx);
        float y0f = floorf(gy);
        float wx1 = gx - x0f;
        float wy1 = gy - y0f;
        float wx0 = 1.0f - wx1;
        float wy0 = 1.0f - wy1;

        int ix0 = (int)x0f;
        int iy0 = (int)y0f;
        int ix1 = ix0 + 1;
        int iy1 = iy0 + 1;

        bool vx0 = (unsigned)ix0 < W;
        bool vx1 = (unsigned)ix1 < W;
        bool vy0 = (unsigned)iy0 < H;
        bool vy1 = (unsigned)iy1 < H;

        m00[j] = (vx0 && vy0) ? wx0 * wy0 : 0.0f;
        m10[j] = (vx1 && vy0) ? wx1 * wy0 : 0.0f;
        m01[j] = (vx0 && vy1) ? wx0 * wy1 : 0.0f;
        m11[j] = (vx1 && vy1) ? wx1 * wy1 : 0.0f;

        unsigned cx0 = (unsigned)min(max(ix0, 0), (int)W - 1);
        unsigned cx1 = (unsigned)min(max(ix1, 0), (int)W - 1);
        unsigned cy0 = (unsigned)min(max(iy0, 0), (int)H - 1);
        unsigned cy1 = (unsigned)min(max(iy1, 0), (int)H - 1);

        o00[j] = cy0 * W + cx0;
        o10[j] = cy0 * W + cx1;
        o01[j] = cy1 * W + cx0;
        o11[j] = cy1 * W + cx1;

        // sigmoid via HW tanh: sigmoid(x) = 0.5*tanh(x/2) + 0.5
        wgt[j] = 0.5f * __tanhf(0.5f * wl[j]) + 0.5f;
        owv[j] = wgt[j] * (m00[j] + m10[j] + m01[j] + m11[j]);
    }

    // store the 3 identical ow planes first (overlaps gather latency,
    // frees owv registers before the gather loop)
    float* out_ow = out + base + hw;
    stg_cs2(out_ow,           owv[0], owv[1]);
    stg_cs2(out_ow + CH,      owv[0], owv[1]);
    stg_cs2(out_ow + 2u * CH, owv[0], owv[1]);

    float*       out_xw = out_ow + HALF;
    const float* xb     = x + base;

#pragma unroll
    for (unsigned c = 0; c < C; c++) {
        const float* xc = xb + c * CH;
        float v00a = __ldg(xc + o00[0]);
        float v10a = __ldg(xc + o10[0]);
        float v01a = __ldg(xc + o01[0]);
        float v11a = __ldg(xc + o11[0]);
        float v00b = __ldg(xc + o00[1]);
        float v10b = __ldg(xc + o10[1]);
        float v01b = __ldg(xc + o01[1]);
        float v11b = __ldg(xc + o11[1]);

        float sa = m00[0] * v00a + m10[0] * v10a + m01[0] * v01a + m11[0] * v11a;
        float sb = m00[1] * v00b + m10[1] * v10b + m01[1] * v01b + m11[1] * v11b;

        stg_cs2(out_xw + c * CH, sa * wgt[0], sb * wgt[1]);
    }
}

extern "C" void kernel_launch(void* const* d_in, const int* in_sizes, int n_in,
                              void* d_out, int out_size)
{
    const float* x = (const float*)d_in[0];
    const float* f = (const float*)d_in[1];
    float* out = (float*)d_out;

    dim3 block(64, 4, 1);
    dim3 grid(W / 128, H / 4, B * T);   // (10, 180, 10)
    ImageBWarp_65343632441725_kernel<<<grid, block>>>(x, f, out);
}

// round 12
// speedup vs baseline: 1.1467x; 1.0297x over previous
#include <cuda_runtime.h>

// Shapes fixed by the problem: x,f = (B=2, 3, T=5, H=720, W=1280) fp32.
// Output = concat(ow, xw), each (B,3,T,H,W) fp32.
//
// Converged optimum (R7): 2 px/thread, 32 regs, ~85% occ, zero-division
// index decode via 3D grid, HW-tanh sigmoid, early ow stores overlapping
// the gather phase, 8-gather batches per channel. Bound by L1tex divergent-
// gather wavefront throughput; DRAM traffic is at the compulsory floor.
constexpr unsigned B  = 2;
constexpr unsigned C  = 3;
constexpr unsigned T  = 5;
constexpr unsigned H  = 720;
constexpr unsigned W  = 1280;
constexpr unsigned PLANE = H * W;            // 921,600
constexpr unsigned CH    = T * PLANE;        // 4,608,000
constexpr unsigned HALF  = B * C * CH;       // 27,648,000

// grid: x -> 10 segments of 128 px, y -> 180 groups of 4 rows, z -> (b,t)
// block: (64, 4) = 256 threads, each thread 2 horizontally adjacent px.

__global__ __launch_bounds__(256)
void ImageBWarp_65343632441725_kernel(const float* __restrict__ x,
                                      const float* __restrict__ f,
                                      float* __restrict__ out)
{
    // zero-division index decode
    unsigned w0 = (blockIdx.x * 64u + threadIdx.x) * 2u;
    unsigned h  = blockIdx.y * 4u + threadIdx.y;
    unsigned bt = blockIdx.z;                 // b*T + t
    unsigned b  = bt / T;
    unsigned base = (bt + b * ((C - 1) * T)) * PLANE;   // (b*C*T + t)*PLANE
    unsigned hw   = h * W + w0;               // 8B-aligned

    const float2 fx2 = *(const float2*)(f + base + hw);
    const float2 fy2 = *(const float2*)(f + base + CH + hw);
    const float2 wl2 = *(const float2*)(f + base + 2u * CH + hw);

    float fx[2] = {fx2.x, fx2.y};
    float fy[2] = {fy2.x, fy2.y};
    float wl[2] = {wl2.x, wl2.y};

    float m00[2], m10[2], m01[2], m11[2];
    unsigned o00[2], o10[2], o01[2], o11[2];
    float wgt[2], owv[2];

#pragma unroll
    for (int j = 0; j < 2; j++) {
        float gx = (float)(w0 + (unsigned)j) + fx[j];
        float gy = (float)h + fy[j];

        float x0f = floorf(gx);
        float y0f = floorf(gy);
        float wx1 = gx - x0f;
        float wy1 = gy - y0f;
        float wx0 = 1.0f - wx1;
        float wy0 = 1.0f - wy1;

        int ix0 = (int)x0f;
        int iy0 = (int)y0f;
        int ix1 = ix0 + 1;
        int iy1 = iy0 + 1;

        bool vx0 = (unsigned)ix0 < W;
        bool vx1 = (unsigned)ix1 < W;
        bool vy0 = (unsigned)iy0 < H;
        bool vy1 = (unsigned)iy1 < H;

        m00[j] = (vx0 && vy0) ? wx0 * wy0 : 0.0f;
        m10[j] = (vx1 && vy0) ? wx1 * wy0 : 0.0f;
        m01[j] = (vx0 && vy1) ? wx0 * wy1 : 0.0f;
        m11[j] = (vx1 && vy1) ? wx1 * wy1 : 0.0f;

        unsigned cx0 = (unsigned)min(max(ix0, 0), (int)W - 1);
        unsigned cx1 = (unsigned)min(max(ix1, 0), (int)W - 1);
        unsigned cy0 = (unsigned)min(max(iy0, 0), (int)H - 1);
        unsigned cy1 = (unsigned)min(max(iy1, 0), (int)H - 1);

        o00[j] = cy0 * W + cx0;
        o10[j] = cy0 * W + cx1;
        o01[j] = cy1 * W + cx0;
        o11[j] = cy1 * W + cx1;

        // sigmoid via HW tanh: sigmoid(x) = 0.5*tanh(x/2) + 0.5
        wgt[j] = 0.5f * __tanhf(0.5f * wl[j]) + 0.5f;
        owv[j] = wgt[j] * (m00[j] + m10[j] + m01[j] + m11[j]);
    }

    // store the 3 identical ow planes first: overlaps with gather latency,
    // frees owv registers before the gather loop
    float* out_ow = out + base + hw;
    {
        float2 ow2 = make_float2(owv[0], owv[1]);
        *(float2*)(out_ow)           = ow2;
        *(float2*)(out_ow + CH)      = ow2;
        *(float2*)(out_ow + 2u * CH) = ow2;
    }

    float*       out_xw = out_ow + HALF;
    const float* xb     = x + base;

#pragma unroll
    for (unsigned c = 0; c < C; c++) {
        const float* xc = xb + c * CH;
        float v00a = __ldg(xc + o00[0]);
        float v10a = __ldg(xc + o10[0]);
        float v01a = __ldg(xc + o01[0]);
        float v11a = __ldg(xc + o11[0]);
        float v00b = __ldg(xc + o00[1]);
        float v10b = __ldg(xc + o10[1]);
        float v01b = __ldg(xc + o01[1]);
        float v11b = __ldg(xc + o11[1]);

        float sa = m00[0] * v00a + m10[0] * v10a + m01[0] * v01a + m11[0] * v11a;
        float sb = m00[1] * v00b + m10[1] * v10b + m01[1] * v01b + m11[1] * v11b;

        *(float2*)(out_xw + c * CH) = make_float2(sa * wgt[0], sb * wgt[1]);
    }
}

extern "C" void kernel_launch(void* const* d_in, const int* in_sizes, int n_in,
                              void* d_out, int out_size)
{
    const float* x = (const float*)d_in[0];
    const float* f = (const float*)d_in[1];
    float* out = (float*)d_out;

    dim3 block(64, 4, 1);
    dim3 grid(W / 128, H / 4, B * T);   // (10, 180, 10)
    ImageBWarp_65343632441725_kernel<<<grid, block>>>(x, f, out);
}